// round 1
// baseline (speedup 1.0000x reference)
#include <cuda_runtime.h>
#include <cstdint>

#define H 512
#define W 512
#define NPIX (H * W)

// Precomputed normalized-location table: L[i*W+j] = (nl1, nl0)
__device__ float2 g_L[NPIX];

__global__ void build_L_kernel(const float* __restrict__ flow) {
    int idx = blockIdx.x * blockDim.x + threadIdx.x;
    if (idx >= NPIX) return;
    int i = idx >> 9;        // row (H dim)
    int j = idx & (W - 1);   // col (W dim)
    float f0 = flow[idx];            // channel 0: added to gy (row index)
    float f1 = flow[NPIX + idx];     // channel 1: added to gx (col index)
    const float s = 2.0f / 511.0f;
    float nl0 = ((float)i + f0) * s - 1.0f;
    float nl1 = ((float)j + f1) * s - 1.0f;
    g_L[idx] = make_float2(nl1, nl0);  // L[..., 0] = nl1, L[..., 1] = nl0
}

__device__ __forceinline__ float2 sample_point(float x, float y, bool bilinear) {
    float2 t;
    if (bilinear) {
        float xt = truncf(x);
        float yt = truncf(y);
        float xf = x - xt;
        float yf = y - yt;
        int x0 = (int)xt;
        int y0 = (int)yt;
        const float2* base = g_L + (x0 << 9) + y0;
        float2 v00 = __ldg(base);
        float2 v01 = __ldg(base + 1);
        float2 v10 = __ldg(base + W);
        float2 v11 = __ldg(base + W + 1);
        float oxf = 1.0f - xf;
        float oyf = 1.0f - yf;
        float w00 = xf * yf;
        float w10 = xf * oyf;
        float w01 = oxf * yf;
        float w11 = oxf * oyf;
        t.x = fmaf(w00, v00.x, fmaf(w10, v10.x, fmaf(w01, v01.x, w11 * v11.x)));
        t.y = fmaf(w00, v00.y, fmaf(w10, v10.y, fmaf(w01, v01.y, w11 * v11.y)));
    } else {
        int xi = min((int)rintf(x), 511);
        int yi = min((int)rintf(y), 511);
        t = __ldg(g_L + (xi << 9) + yi);
    }
    // out0 = (tmp[:,1]+1)/2*512 ; out1 = (tmp[:,0]+1)/2*512
    return make_float2(fmaf(t.y, 256.0f, 256.0f), fmaf(t.x, 256.0f, 256.0f));
}

__global__ void sample_kernel(const float4* __restrict__ pts,
                              float4* __restrict__ out,
                              const int* __restrict__ intep,
                              int n_vec) {
    int idx = blockIdx.x * blockDim.x + threadIdx.x;
    if (idx >= n_vec) return;
    bool bilinear = (*intep) != 0;
    float4 p = pts[idx];  // two points: (x0,y0,x1,y1)
    float2 r0 = sample_point(p.x, p.y, bilinear);
    float2 r1 = sample_point(p.z, p.w, bilinear);
    out[idx] = make_float4(r0.x, r0.y, r1.x, r1.y);
}

extern "C" void kernel_launch(void* const* d_in, const int* in_sizes, int n_in,
                              void* d_out, int out_size) {
    const float* point = (const float*)d_in[0];   // (1, N, 2)
    const float* flow  = (const float*)d_in[1];   // (1, 2, 512, 512)
    const int*   intep = (const int*)d_in[2];

    // Build normalized-location table
    build_L_kernel<<<(NPIX + 255) / 256, 256>>>(flow);

    // Sample: out_size = N*2 floats; each float4 covers 2 points
    int n_vec = out_size / 4;
    sample_kernel<<<(n_vec + 255) / 256, 256>>>(
        (const float4*)point, (float4*)d_out, intep, n_vec);
}

// round 2
// speedup vs baseline: 1.5005x; 1.5005x over previous
#include <cuda_runtime.h>
#include <cstdint>

#define H 512
#define W 512
#define NPIX (H * W)

// Packed corner table: entry (i,j) = 32 bytes =
//   float4 lo = (L[i][j].x,   L[i][j].y,   L[i][j+1].x,   L[i][j+1].y)
//   float4 hi = (L[i+1][j].x, L[i+1][j].y, L[i+1][j+1].x, L[i+1][j+1].y)
// where L[i][j] = (nl1, nl0). 32B-aligned -> one L2 sector per bilinear sample.
__device__ float4 g_T[NPIX * 2];

__device__ __forceinline__ float2 nl_at(const float* __restrict__ flow, int i, int j) {
    int idx = (i << 9) | j;
    float f0 = flow[idx];          // channel 0 (row offset)
    float f1 = flow[NPIX + idx];   // channel 1 (col offset)
    const float s = 2.0f / 511.0f;
    float nl0 = fmaf((float)i + f0, s, -1.0f);
    float nl1 = fmaf((float)j + f1, s, -1.0f);
    return make_float2(nl1, nl0);
}

__global__ void build_T_kernel(const float* __restrict__ flow) {
    int idx = blockIdx.x * blockDim.x + threadIdx.x;
    if (idx >= NPIX) return;
    int i = idx >> 9;
    int j = idx & (W - 1);
    int i1 = min(i + 1, H - 1);
    int j1 = min(j + 1, W - 1);
    float2 v00 = nl_at(flow, i,  j);
    float2 v01 = nl_at(flow, i,  j1);
    float2 v10 = nl_at(flow, i1, j);
    float2 v11 = nl_at(flow, i1, j1);
    g_T[idx * 2]     = make_float4(v00.x, v00.y, v01.x, v01.y);
    g_T[idx * 2 + 1] = make_float4(v10.x, v10.y, v11.x, v11.y);
}

__device__ __forceinline__ float2 sample_point(float x, float y, bool bilinear) {
    float2 t;
    if (bilinear) {
        float xt = truncf(x);
        float yt = truncf(y);
        float xf = x - xt;
        float yf = y - yt;
        int x0 = (int)xt;
        int y0 = (int)yt;
        int key = (x0 << 9) | y0;
        float4 lo = __ldg(g_T + key * 2);       // v00, v01
        float4 hi = __ldg(g_T + key * 2 + 1);   // v10, v11
        float oxf = 1.0f - xf;
        float oyf = 1.0f - yf;
        float w00 = xf * yf;
        float w10 = xf * oyf;
        float w01 = oxf * yf;
        float w11 = oxf * oyf;
        t.x = fmaf(w00, lo.x, fmaf(w10, hi.x, fmaf(w01, lo.z, w11 * hi.z)));
        t.y = fmaf(w00, lo.y, fmaf(w10, hi.y, fmaf(w01, lo.w, w11 * hi.w)));
    } else {
        int xi = min((int)rintf(x), 511);
        int yi = min((int)rintf(y), 511);
        float4 lo = __ldg(g_T + ((xi << 9) | yi) * 2);
        t = make_float2(lo.x, lo.y);
    }
    // out0 = (tmp[:,1]+1)/2*512 ; out1 = (tmp[:,0]+1)/2*512
    return make_float2(fmaf(t.y, 256.0f, 256.0f), fmaf(t.x, 256.0f, 256.0f));
}

__global__ void sample_kernel(const float4* __restrict__ pts,
                              float4* __restrict__ out,
                              const int* __restrict__ intep,
                              int n_vec) {
    int idx = blockIdx.x * blockDim.x + threadIdx.x;
    if (idx >= n_vec) return;
    bool bilinear = (*intep) != 0;
    float4 p = pts[idx];  // two points: (x0,y0,x1,y1)
    float2 r0 = sample_point(p.x, p.y, bilinear);
    float2 r1 = sample_point(p.z, p.w, bilinear);
    out[idx] = make_float4(r0.x, r0.y, r1.x, r1.y);
}

extern "C" void kernel_launch(void* const* d_in, const int* in_sizes, int n_in,
                              void* d_out, int out_size) {
    const float* point = (const float*)d_in[0];   // (1, N, 2)
    const float* flow  = (const float*)d_in[1];   // (1, 2, 512, 512)
    const int*   intep = (const int*)d_in[2];

    build_T_kernel<<<(NPIX + 255) / 256, 256>>>(flow);

    int n_vec = out_size / 4;  // 2 points per float4
    sample_kernel<<<(n_vec + 255) / 256, 256>>>(
        (const float4*)point, (float4*)d_out, intep, n_vec);
}

// round 3
// speedup vs baseline: 1.8213x; 1.2138x over previous
#include <cuda_runtime.h>
#include <cuda_fp16.h>
#include <cstdint>

#define H 512
#define W 512
#define NPIX (H * W)

// Packed flow-corner table: entry (i,j) = 16 bytes =
//   half2 f(i,j), half2 f(i,j+1), half2 f(i+1,j), half2 f(i+1,j+1)
// where f = (flow_ch0, flow_ch1). One LDG.128 per bilinear sample.
__device__ uint4 g_F[NPIX];   // 4 MB, lives in L2

__device__ __forceinline__ uint32_t pack_h2(float a, float b) {
    __half2 h = __floats2half2_rn(a, b);
    return *reinterpret_cast<uint32_t*>(&h);
}

__global__ void build_F_kernel(const float* __restrict__ flow) {
    int idx = blockIdx.x * blockDim.x + threadIdx.x;
    if (idx >= NPIX) return;
    int i = idx >> 9;
    int j = idx & (W - 1);
    int i1 = min(i + 1, H - 1);
    int j1 = min(j + 1, W - 1);
    int p00 = (i  << 9) | j;
    int p01 = (i  << 9) | j1;
    int p10 = (i1 << 9) | j;
    int p11 = (i1 << 9) | j1;
    uint4 e;
    e.x = pack_h2(flow[p00], flow[NPIX + p00]);
    e.y = pack_h2(flow[p01], flow[NPIX + p01]);
    e.z = pack_h2(flow[p10], flow[NPIX + p10]);
    e.w = pack_h2(flow[p11], flow[NPIX + p11]);
    g_F[idx] = e;
}

__device__ __forceinline__ float2 unpack_h2(uint32_t u) {
    __half2 h = *reinterpret_cast<__half2*>(&u);
    return __half22float2(h);
}

// SCALE = (2/511)/2*512
#define OUT_SCALE (512.0f / 511.0f)

__device__ __forceinline__ float2 sample_point(float x, float y, bool bilinear) {
    if (bilinear) {
        float xt = truncf(x);
        float yt = truncf(y);
        float xf = x - xt;
        float yf = y - yt;
        int x0 = (int)xt;
        int y0 = (int)yt;
        uint4 e = __ldg(g_F + ((x0 << 9) | y0));
        float2 c00 = unpack_h2(e.x);   // f at (x0,y0)
        float2 c01 = unpack_h2(e.y);   // f at (x0,y1)
        float2 c10 = unpack_h2(e.z);   // f at (x1,y0)
        float2 c11 = unpack_h2(e.w);   // f at (x1,y1)
        float oxf = 1.0f - xf;
        float oyf = 1.0f - yf;
        float w00 = xf * yf;
        float w10 = xf * oyf;
        float w01 = oxf * yf;
        float w11 = oxf * oyf;
        // bilinear(flow) for both channels
        float bf0 = fmaf(w00, c00.x, fmaf(w10, c10.x, fmaf(w01, c01.x, w11 * c11.x)));
        float bf1 = fmaf(w00, c00.y, fmaf(w10, c10.y, fmaf(w01, c01.y, w11 * c11.y)));
        // analytic grid part:  row = x0 + 1 - yf,  col = y0 + 1 - xf
        float out0 = ((float)(x0 + 1) - yf + bf0) * OUT_SCALE;
        float out1 = ((float)(y0 + 1) - xf + bf1) * OUT_SCALE;
        return make_float2(out0, out1);
    } else {
        int xi = min((int)rintf(x), H - 1);
        int yi = min((int)rintf(y), W - 1);
        uint4 e = __ldg(g_F + ((xi << 9) | yi));
        float2 c00 = unpack_h2(e.x);   // f at (xi,yi)
        float out0 = ((float)xi + c00.x) * OUT_SCALE;
        float out1 = ((float)yi + c00.y) * OUT_SCALE;
        return make_float2(out0, out1);
    }
}

__global__ void sample_kernel(const float4* __restrict__ pts,
                              float4* __restrict__ out,
                              const int* __restrict__ intep,
                              int n_vec) {
    int idx = blockIdx.x * blockDim.x + threadIdx.x;
    if (idx >= n_vec) return;
    bool bilinear = (*intep) != 0;
    float4 p = pts[idx];  // two points: (x0,y0,x1,y1)
    float2 r0 = sample_point(p.x, p.y, bilinear);
    float2 r1 = sample_point(p.z, p.w, bilinear);
    out[idx] = make_float4(r0.x, r0.y, r1.x, r1.y);
}

extern "C" void kernel_launch(void* const* d_in, const int* in_sizes, int n_in,
                              void* d_out, int out_size) {
    const float* point = (const float*)d_in[0];   // (1, N, 2)
    const float* flow  = (const float*)d_in[1];   // (1, 2, 512, 512)
    const int*   intep = (const int*)d_in[2];

    build_F_kernel<<<(NPIX + 255) / 256, 256>>>(flow);

    int n_vec = out_size / 4;  // 2 points per float4
    sample_kernel<<<(n_vec + 255) / 256, 256>>>(
        (const float4*)point, (float4*)d_out, intep, n_vec);
}